// round 5
// baseline (speedup 1.0000x reference)
#include <cuda_runtime.h>

// x: (2,8,4,256,384) fp32 -> 16 independent DxHxW volumes
#define WD   384
#define HT   256
#define DP   4
#define HW   (HT*WD)          // 98304
#define DHW  (DP*HW)          // 393216
#define NIMG 16

#define OUTW   30             // output columns per warp strip (lanes 1..30)
#define NSTRIP 13             // ceil(384/30)
#define CH     16             // output rows per h-chunk
#define NCH    (HT/CH)        // 16
#define WPB    4              // warps per block
#define NTASK  (NSTRIP*NCH*NIMG)   // 3328 warps

#define BONUS 10.0f
#define FULL  0xffffffffu

__global__ __launch_bounds__(128, 6)
void cqi_kernel(const float* __restrict__ xg, float* __restrict__ out)
{
    const int gw   = blockIdx.x * WPB + (threadIdx.x >> 5);
    const int lane = threadIdx.x & 31;

    const int img   = gw / (NSTRIP * NCH);
    const int rem   = gw - img * (NSTRIP * NCH);
    const int strip = rem % NSTRIP;
    const int hc    = rem / NSTRIP;

    const int w0   = strip * OUTW;
    const int wout = w0 + lane - 1;                 // this lane's output w
    const bool active = (lane >= 1) && (lane <= 30) && (wout < WD);
    int wcol = wout; if (wcol < 0) wcol = 0; if (wcol > WD-1) wcol = WD-1;

    const int h0 = hc * CH;

    const float* __restrict__ xin = xg + (size_t)img * DHW + wcol;

    // rolling 3-row window, per plane p=0..3:
    float valU[4], lfU[4], rgU[4], wmU[4];   // row h-1
    float valM[4], lfM[4], rgM[4], wmM[4];   // row h
    float valD[4], lfD[4], rgD[4], wmD[4];   // row h+1
    float pend[4];                           // raw prefetch of next row

    #define LOADROW(HR, DST)                                             \
        do {                                                             \
            const float* _p = xin + (HR) * WD;                           \
            (DST)[0] = __ldg(_p);                                        \
            (DST)[1] = __ldg(_p + HW);                                   \
            (DST)[2] = __ldg(_p + 2*HW);                                 \
            (DST)[3] = __ldg(_p + 3*HW);                                 \
        } while (0)

    // from raw[4]: shifted copies via shfl; NMS w-max via fmax only
    // (max commutes with shfl: hmax3 = max(lf,val,rg), then plane triples)
    #define COMMIT(RAW, V, LF, RG, WM)                                   \
        do {                                                             \
            _Pragma("unroll")                                            \
            for (int p = 0; p < 4; ++p) {                                \
                float _v = (RAW)[p];                                     \
                (V)[p]  = _v;                                            \
                (LF)[p] = __shfl_up_sync(FULL, _v, 1);                   \
                (RG)[p] = __shfl_down_sync(FULL, _v, 1);                 \
            }                                                            \
            float _h0 = fmaxf(fmaxf((LF)[0], (V)[0]), (RG)[0]);          \
            float _h1 = fmaxf(fmaxf((LF)[1], (V)[1]), (RG)[1]);          \
            float _h2 = fmaxf(fmaxf((LF)[2], (V)[2]), (RG)[2]);          \
            float _h3 = fmaxf(fmaxf((LF)[3], (V)[3]), (RG)[3]);          \
            float _m01 = fmaxf(_h0, _h1);                                \
            float _m12 = fmaxf(_h1, _h2);                                \
            float _m23 = fmaxf(_h2, _h3);                                \
            (WM)[0] = _m01;                                              \
            (WM)[1] = fmaxf(_m01, _h2);                                  \
            (WM)[2] = fmaxf(_m12, _h3);                                  \
            (WM)[3] = _m23;                                              \
        } while (0)

    // ---- prologue: rows h0-1 and h0 ----
    {
        float ra[4], rb[4];
        int r_up = h0 - 1; if (r_up < 0) r_up = 0;
        LOADROW(r_up, ra);
        LOADROW(h0,  rb);
        COMMIT(ra, valU, lfU, rgU, wmU);
        COMMIT(rb, valM, lfM, rgM, wmM);
        int r_dn = h0 + 1; if (r_dn > HT-1) r_dn = HT-1;
        LOADROW(r_dn, pend);
    }

    float* __restrict__ oc0 = out + (size_t)img * 3 * DHW;
    float* __restrict__ oy  = out + (size_t)NIMG * 3 * DHW + (size_t)img * DHW;

    const int PA[4] = {0, 0, 1, 2};    // clamped plane d-1
    const int PC[4] = {1, 2, 3, 3};    // clamped plane d+1

    int obase = h0 * WD + wout;

    #pragma unroll 4
    for (int i = 0; i < CH; ++i) {
        const int h = h0 + i;

        // consume prefetch, issue next prefetch (row h+2, clamped)
        float tmp[4];
        #pragma unroll
        for (int p = 0; p < 4; ++p) tmp[p] = pend[p];
        int rn = h + 2; if (rn > HT-1) rn = HT-1;
        LOADROW(rn, pend);
        COMMIT(tmp, valD, lfD, rgD, wmD);

        #pragma unroll
        for (int d = 0; d < DP; ++d) {
            const int pa = PA[d], pc = PC[d];
            const float xc = valM[d];

            const float b0 = 0.5f * (rgM[d] - lfM[d]);        // dx
            const float b1 = 0.5f * (valD[d] - valU[d]);      // dy
            const float b2 = 0.5f * (valM[pa] - valM[pc]);    // ds (flipped)

            const float dxx = rgM[d]   - 2.0f*xc + lfM[d];
            const float dyy = valD[d]  - 2.0f*xc + valU[d];
            const float dss = valM[pc] - 2.0f*xc + valM[pa];
            const float dxy = 0.25f * ( lfU[d] - rgU[d] - lfD[d] + rgD[d]);
            const float dys = 0.25f * (-valU[pa] + valD[pa] + valU[pc] - valD[pc]);
            const float dxs = 0.25f * (-lfM[pa] + rgM[pa] + lfM[pc] - rgM[pc]);

            const float mx = fmaxf(fmaxf(wmU[d], wmM[d]), wmD[d]);
            const bool nms = (xc == mx);

            const float c00 = dyy*dss - dys*dys;
            const float c01 = dxs*dys - dxy*dss;
            const float c02 = dxy*dys - dxs*dyy;
            const float c11 = dxx*dss - dxs*dxs;
            const float c12 = dxy*dxs - dxx*dys;
            const float c22 = dxx*dyy - dxy*dxy;
            const float det = dxx*c00 + dxy*c01 + dxs*c02;

            const bool ok = nms && (det != 0.0f);
            const float invdet = __fdividef(1.0f, (det == 0.0f) ? 1.0f : det);

            const float u0 = (c00*b0 + c01*b1 + c02*b2) * invdet;
            const float u1 = (c01*b0 + c11*b1 + c12*b2) * invdet;
            const float u2 = (c02*b0 + c12*b1 + c22*b2) * invdet;

            float d0 = ok ? -u0 : 0.0f;
            float d1 = ok ? -u1 : 0.0f;
            float d2 = ok ? -u2 : 0.0f;

            const bool small = fmaxf(fmaxf(fabsf(d0), fabsf(d1)), fabsf(d2)) <= 0.7f;
            d0 = small ? d0 : 0.0f;
            d1 = small ? d1 : 0.0f;
            d2 = small ? d2 : 0.0f;

            const float dE = 0.5f * (b0*d0 + b1*d1 + b2*d2);

            if (active) {
                const int o = obase + d * HW;
                oc0[o + 0*DHW] = (float)d + d2;
                oc0[o + 1*DHW] = (float)wout + d0;
                oc0[o + 2*DHW] = (float)h + d1;
                oy [o]         = xc + dE + (ok ? BONUS : 0.0f);
            }
        }
        obase += WD;

        // rotate rolling window: U <- M <- D
        #pragma unroll
        for (int p = 0; p < 4; ++p) {
            valU[p]=valM[p]; lfU[p]=lfM[p]; rgU[p]=rgM[p]; wmU[p]=wmM[p];
            valM[p]=valD[p]; lfM[p]=lfD[p]; rgM[p]=rgD[p]; wmM[p]=wmD[p];
        }
    }
    #undef LOADROW
    #undef COMMIT
}

extern "C" void kernel_launch(void* const* d_in, const int* in_sizes, int n_in,
                              void* d_out, int out_size)
{
    const float* x = (const float*)d_in[0];
    float* out = (float*)d_out;
    dim3 block(WPB * 32, 1, 1);
    dim3 grid(NTASK / WPB, 1, 1);
    cqi_kernel<<<grid, block>>>(x, out);
}

// round 6
// speedup vs baseline: 1.1127x; 1.1127x over previous
#include <cuda_runtime.h>

// x: (2,8,4,256,384) fp32 -> 16 independent DxHxW volumes
#define WD   384
#define HT   256
#define DP   4
#define HW   (HT*WD)          // 98304
#define DHW  (DP*HW)          // 393216
#define NIMG 16

#define OUTW   30             // output columns per warp strip (lanes 1..30)
#define NSTRIP 13             // ceil(384/30)
#define CH     8              // output rows per h-chunk
#define NCH    (HT/CH)        // 32
#define WPB    4              // warps per block
#define NTASK  (NSTRIP*NCH*NIMG)   // 6656 warps

#define BONUS 10.0f
#define FULL  0xffffffffu

__global__ __launch_bounds__(128, 6)
void cqi_kernel(const float* __restrict__ xg, float* __restrict__ out)
{
    const int gw   = blockIdx.x * WPB + (threadIdx.x >> 5);
    const int lane = threadIdx.x & 31;

    const int img   = gw / (NSTRIP * NCH);
    const int rem   = gw - img * (NSTRIP * NCH);
    const int strip = rem % NSTRIP;
    const int hc    = rem / NSTRIP;

    const int w0   = strip * OUTW;
    const int wout = w0 + lane - 1;                 // this lane's output w
    const bool active = (lane >= 1) && (lane <= 30) && (wout < WD);
    int wcol = wout; if (wcol < 0) wcol = 0; if (wcol > WD-1) wcol = WD-1;

    const int h0 = hc * CH;

    const float* __restrict__ xin = xg + (size_t)img * DHW + wcol;

    // 3-slot rolling row window, slot selected by compile-time (i+k)%3:
    float val[3][4], lf[3][4], rg[3][4], wm[3][4];
    float pend[4];                                  // raw prefetch of next row

    #define LOADROW(HR, DST)                                             \
        do {                                                             \
            const float* _p = xin + (HR) * WD;                           \
            (DST)[0] = __ldg(_p);                                        \
            (DST)[1] = __ldg(_p + HW);                                   \
            (DST)[2] = __ldg(_p + 2*HW);                                 \
            (DST)[3] = __ldg(_p + 3*HW);                                 \
        } while (0)

    // from raw[4] into slot S: shifted copies via shfl; NMS w-max via fmax only
    #define COMMIT(RAW, S)                                               \
        do {                                                             \
            _Pragma("unroll")                                            \
            for (int p = 0; p < 4; ++p) {                                \
                float _v = (RAW)[p];                                     \
                val[S][p] = _v;                                          \
                lf[S][p]  = __shfl_up_sync(FULL, _v, 1);                 \
                rg[S][p]  = __shfl_down_sync(FULL, _v, 1);               \
            }                                                            \
            float _h0 = fmaxf(fmaxf(lf[S][0], val[S][0]), rg[S][0]);     \
            float _h1 = fmaxf(fmaxf(lf[S][1], val[S][1]), rg[S][1]);     \
            float _h2 = fmaxf(fmaxf(lf[S][2], val[S][2]), rg[S][2]);     \
            float _h3 = fmaxf(fmaxf(lf[S][3], val[S][3]), rg[S][3]);     \
            float _m01 = fmaxf(_h0, _h1);                                \
            float _m12 = fmaxf(_h1, _h2);                                \
            float _m23 = fmaxf(_h2, _h3);                                \
            wm[S][0] = _m01;                                             \
            wm[S][1] = fmaxf(_m01, _h2);                                 \
            wm[S][2] = fmaxf(_m12, _h3);                                 \
            wm[S][3] = _m23;                                             \
        } while (0)

    // ---- prologue: rows h0-1 (slot 0) and h0 (slot 1) ----
    {
        float ra[4], rb[4];
        int r_up = h0 - 1; if (r_up < 0) r_up = 0;
        LOADROW(r_up, ra);
        LOADROW(h0,  rb);
        COMMIT(ra, 0);
        COMMIT(rb, 1);
        int r_dn = h0 + 1; if (r_dn > HT-1) r_dn = HT-1;
        LOADROW(r_dn, pend);
    }

    float* __restrict__ oc0 = out + (size_t)img * 3 * DHW;
    float* __restrict__ oy  = out + (size_t)NIMG * 3 * DHW + (size_t)img * DHW;

    const int PA[4] = {0, 0, 1, 2};    // clamped plane d-1
    const int PC[4] = {1, 2, 3, 3};    // clamped plane d+1

    int obase = h0 * WD + wout;

    #pragma unroll
    for (int i = 0; i < CH; ++i) {
        const int h  = h0 + i;
        const int sU = i % 3;           // row h-1
        const int sM = (i + 1) % 3;     // row h
        const int sD = (i + 2) % 3;     // row h+1 (written now)

        // consume prefetch into slot sD, issue next prefetch (row h+2, clamped)
        float tmp[4];
        #pragma unroll
        for (int p = 0; p < 4; ++p) tmp[p] = pend[p];
        int rn = h + 2; if (rn > HT-1) rn = HT-1;
        LOADROW(rn, pend);
        COMMIT(tmp, sD);

        #pragma unroll
        for (int d = 0; d < DP; ++d) {
            const int pa = PA[d], pc = PC[d];
            const float xc = val[sM][d];

            const float b0 = 0.5f * (rg[sM][d] - lf[sM][d]);       // dx
            const float b1 = 0.5f * (val[sD][d] - val[sU][d]);     // dy
            const float b2 = 0.5f * (val[sM][pa] - val[sM][pc]);   // ds (flipped)

            const float dxx = rg[sM][d]   - 2.0f*xc + lf[sM][d];
            const float dyy = val[sD][d]  - 2.0f*xc + val[sU][d];
            const float dss = val[sM][pc] - 2.0f*xc + val[sM][pa];
            const float dxy = 0.25f * ( lf[sU][d] - rg[sU][d] - lf[sD][d] + rg[sD][d]);
            const float dys = 0.25f * (-val[sU][pa] + val[sD][pa] + val[sU][pc] - val[sD][pc]);
            const float dxs = 0.25f * (-lf[sM][pa] + rg[sM][pa] + lf[sM][pc] - rg[sM][pc]);

            const float mx = fmaxf(fmaxf(wm[sU][d], wm[sM][d]), wm[sD][d]);
            const bool nms = (xc == mx);

            const float c00 = dyy*dss - dys*dys;
            const float c01 = dxs*dys - dxy*dss;
            const float c02 = dxy*dys - dxs*dyy;
            const float c11 = dxx*dss - dxs*dxs;
            const float c12 = dxy*dxs - dxx*dys;
            const float c22 = dxx*dyy - dxy*dxy;
            const float det = dxx*c00 + dxy*c01 + dxs*c02;

            const bool ok = nms && (det != 0.0f);
            const float invdet = __fdividef(1.0f, (det == 0.0f) ? 1.0f : det);

            const float u0 = (c00*b0 + c01*b1 + c02*b2) * invdet;
            const float u1 = (c01*b0 + c11*b1 + c12*b2) * invdet;
            const float u2 = (c02*b0 + c12*b1 + c22*b2) * invdet;

            float d0 = ok ? -u0 : 0.0f;
            float d1 = ok ? -u1 : 0.0f;
            float d2 = ok ? -u2 : 0.0f;

            const bool small = fmaxf(fmaxf(fabsf(d0), fabsf(d1)), fabsf(d2)) <= 0.7f;
            d0 = small ? d0 : 0.0f;
            d1 = small ? d1 : 0.0f;
            d2 = small ? d2 : 0.0f;

            const float dE = 0.5f * (b0*d0 + b1*d1 + b2*d2);

            if (active) {
                const int o = obase + d * HW;
                oc0[o + 0*DHW] = (float)d + d2;
                oc0[o + 1*DHW] = (float)wout + d0;
                oc0[o + 2*DHW] = (float)h + d1;
                oy [o]         = xc + dE + (ok ? BONUS : 0.0f);
            }
        }
        obase += WD;
    }
    #undef LOADROW
    #undef COMMIT
}

extern "C" void kernel_launch(void* const* d_in, const int* in_sizes, int n_in,
                              void* d_out, int out_size)
{
    const float* x = (const float*)d_in[0];
    float* out = (float*)d_out;
    dim3 block(WPB * 32, 1, 1);
    dim3 grid(NTASK / WPB, 1, 1);
    cqi_kernel<<<grid, block>>>(x, out);
}